// round 3
// baseline (speedup 1.0000x reference)
#include <cuda_runtime.h>
#include <cstdint>

#define LAYERS 8
#define EPS_F 1e-7f

typedef unsigned long long ull;

__device__ __forceinline__ ull pack2(float x, float y) {
    ull r; asm("mov.b64 %0, {%1, %2};" : "=l"(r) : "f"(x), "f"(y)); return r;
}
__device__ __forceinline__ void unpack2(ull v, float& x, float& y) {
    asm("mov.b64 {%0, %1}, %2;" : "=f"(x), "=f"(y) : "l"(v));
}
__device__ __forceinline__ ull fma2(ull a, ull b, ull c) {
    ull d; asm("fma.rn.f32x2 %0, %1, %2, %3;" : "=l"(d) : "l"(a), "l"(b), "l"(c)); return d;
}
__device__ __forceinline__ ull mul2(ull a, ull b) {
    ull d; asm("mul.rn.f32x2 %0, %1, %2;" : "=l"(d) : "l"(a), "l"(b)); return d;
}

// ---------------------------------------------------------------------------
// Fused kernel. Per-block cooperative precompute of the 3 folded circuit
// matrices (column phases {1,-i,-i,-1} folded in), stored as packed
// (re,im) 64-bit words; then grid-stride main loop, 4 elements/group,
// packed f32x2 complex mat-vec.
// out layout: [pi (B,3) | mu (B,3) | sigma (B,3)], row-major.
// ---------------------------------------------------------------------------
__global__ void __launch_bounds__(256, 2)
qmdn_fused(const float4* __restrict__ x4,
           const float* __restrict__ wp,
           const float* __restrict__ wm,
           const float* __restrict__ ws,
           float* __restrict__ out, int B) {
    __shared__ float sR[3][LAYERS][2][2][2][2];   // q, layer, wire, row, col, re/im
    __shared__ float sP[3][LAYERS][4][4][2];      // workspace for layer products
    __shared__ ull   sM[3][16];                   // final folded matrices, packed (re,im)

    int tid  = threadIdx.x;
    int wid  = tid >> 5;
    int lane = tid & 31;

    if (wid < 3) {
        int q = wid;
        const float* w = (q == 0) ? wp : (q == 1) ? wm : ws;

        // 1. all 16 Rot gates in parallel (lane = 2*layer + wire)
        if (lane < 16) {
            int l = lane >> 1, wi = lane & 1;
            float phi = w[(l * 2 + wi) * 3 + 0];
            float th  = w[(l * 2 + wi) * 3 + 1];
            float om  = w[(l * 2 + wi) * 3 + 2];
            float st, ct, sapo, capo, samo, camo;
            __sincosf(0.5f * th, &st, &ct);
            __sincosf(0.5f * (phi + om), &sapo, &capo);
            __sincosf(0.5f * (phi - om), &samo, &camo);
            sR[q][l][wi][0][0][0] =  capo * ct;  sR[q][l][wi][0][0][1] = -sapo * ct;
            sR[q][l][wi][0][1][0] = -camo * st;  sR[q][l][wi][0][1][1] = -samo * st;
            sR[q][l][wi][1][0][0] =  camo * st;  sR[q][l][wi][1][0][1] = -samo * st;
            sR[q][l][wi][1][1][0] =  capo * ct;  sR[q][l][wi][1][1][1] =  sapo * ct;
        }
        __syncwarp();

        // 2. per-layer PK = row-permuted Kronecker (lane = 4*r + c)
        if (lane < 16) {
            int r = lane >> 2, c = lane & 3;
            const int src[4] = {0, 2, 3, 1};
            int rs = src[r], i0 = rs >> 1, j0 = rs & 1, i1 = c >> 1, j1 = c & 1;
#pragma unroll
            for (int l = 0; l < LAYERS; l++) {
                float ar = sR[q][l][0][i0][i1][0], ai = sR[q][l][0][i0][i1][1];
                float br = sR[q][l][1][j0][j1][0], bi = sR[q][l][1][j0][j1][1];
                sP[q][l][r][c][0] = ar * br - ai * bi;
                sP[q][l][r][c][1] = ar * bi + ai * br;
            }
        }
        __syncwarp();

        // 3. log-tree product: U = PK7 * PK6 * ... * PK0
        for (int np = 4; np >= 1; np >>= 1) {
            float res[4][2];
            if (lane < 16) {
                int r = lane >> 2, c = lane & 3;
                for (int m = 0; m < np; m++) {
                    float sr = 0.f, si = 0.f;
#pragma unroll
                    for (int k = 0; k < 4; k++) {
                        float ar = sP[q][2 * m + 1][r][k][0], ai = sP[q][2 * m + 1][r][k][1];
                        float br = sP[q][2 * m][k][c][0],     bi = sP[q][2 * m][k][c][1];
                        sr += ar * br - ai * bi;
                        si += ar * bi + ai * br;
                    }
                    res[m][0] = sr; res[m][1] = si;
                }
            }
            __syncwarp();
            if (lane < 16) {
                int r = lane >> 2, c = lane & 3;
                for (int m = 0; m < np; m++) {
                    sP[q][m][r][c][0] = res[m][0];
                    sP[q][m][r][c][1] = res[m][1];
                }
            }
            __syncwarp();
        }

        // 4. fold column phases {1, -i, -i, -1}, pack (re,im)
        if (lane < 16) {
            int r = lane >> 2, c = lane & 3;
            float ur = sP[q][0][r][c][0], ui = sP[q][0][r][c][1];
            float mr, mi;
            if (c == 0)      { mr =  ur; mi =  ui; }
            else if (c == 3) { mr = -ur; mi = -ui; }
            else             { mr =  ui; mi = -ur; }   // -i*(a+bi) = b - a i
            sM[q][r * 4 + c] = pack2(mr, mi);
        }
    }
    __syncthreads();

    // ------------------- main loop: grid-stride, 4 elems/group -------------------
    int nGroups = B >> 2;
    int stride  = gridDim.x * blockDim.x;
    const float CLIP_LO = EPS_F;
    const float CLIP_HI = 1.0f - EPS_F;
    size_t regionStride = 3 * (size_t)B;

    for (int t = blockIdx.x * blockDim.x + tid; t < nGroups; t += stride) {
        float4 xv = x4[t];
        float xs[4] = {xv.x, xv.y, xv.z, xv.w};

        // packed duplicated amplitudes: adup[e][k] = (a, a)
        ull adup[4][4];
#pragma unroll
        for (int e = 0; e < 4; e++) {
            float s0, c0, s1, c1;
            __sincosf(0.5f * xs[e], &s0, &c0);
            __sincosf(0.78539816339744831f * xs[e], &s1, &c1);
            adup[e][0] = pack2(c0 * c1, c0 * c1);
            adup[e][1] = pack2(c0 * s1, c0 * s1);
            adup[e][2] = pack2(s0 * c1, s0 * c1);
            adup[e][3] = pack2(s0 * s1, s0 * s1);
        }

#pragma unroll
        for (int q = 0; q < 3; q++) {
            ull m[16];
#pragma unroll
            for (int i = 0; i < 16; i++) m[i] = sM[q][i];

            float o[12];
#pragma unroll
            for (int e = 0; e < 4; e++) {
                float p[4];
                int nrows = (q == 0) ? 3 : 4;
#pragma unroll
                for (int j = 0; j < 4; j++) {
                    if (j >= nrows) break;
                    ull acc = mul2(m[j * 4 + 0], adup[e][0]);
                    acc = fma2(m[j * 4 + 1], adup[e][1], acc);
                    acc = fma2(m[j * 4 + 2], adup[e][2], acc);
                    acc = fma2(m[j * 4 + 3], adup[e][3], acc);
                    float re, im;
                    unpack2(acc, re, im);
                    p[j] = fmaf(re, re, im * im);
                }
                if (q == 0) {
                    float inv = __fdividef(1.0f, p[0] + p[1] + p[2]);
                    o[e * 3 + 0] = p[0] * inv;
                    o[e * 3 + 1] = p[1] * inv;
                    o[e * 3 + 2] = p[2] * inv;
                } else {
                    float pc[4];
#pragma unroll
                    for (int j = 0; j < 4; j++)
                        pc[j] = fminf(fmaxf(p[j], CLIP_LO), CLIP_HI);
                    if (q == 1) {
                        float l3 = __logf(pc[3]);
                        o[e * 3 + 0] = __logf(pc[0]) - l3;
                        o[e * 3 + 1] = __logf(pc[1]) - l3;
                        o[e * 3 + 2] = __logf(pc[2]) - l3;
                    } else {
                        float inv = __fdividef(1.0f, pc[3]);
                        o[e * 3 + 0] = pc[0] * inv;
                        o[e * 3 + 1] = pc[1] * inv;
                        o[e * 3 + 2] = pc[2] * inv;
                    }
                }
            }
            float4* dst = (float4*)(out + q * regionStride + (size_t)t * 12);
            dst[0] = make_float4(o[0], o[1], o[2],  o[3]);
            dst[1] = make_float4(o[4], o[5], o[6],  o[7]);
            dst[2] = make_float4(o[8], o[9], o[10], o[11]);
        }
    }
}

extern "C" void kernel_launch(void* const* d_in, const int* in_sizes, int n_in,
                              void* d_out, int out_size) {
    const float* x  = (const float*)d_in[0];
    const float* wp = (const float*)d_in[1];
    const float* wm = (const float*)d_in[2];
    const float* ws = (const float*)d_in[3];
    float* out = (float*)d_out;
    int B = in_sizes[0];

    int threads = 256;
    int blocks = 512;    // 2 groups per thread at B = 2^20; prologue amortized 2x
    qmdn_fused<<<blocks, threads>>>((const float4*)x, wp, wm, ws, out, B);
}